// round 12
// baseline (speedup 1.0000x reference)
#include <cuda_runtime.h>
#include <float.h>

#define BB 4096
#define NN 2048
#define NPAIR 3
#define ROW_THREADS 256          // 256 thr * 8 floats = 2048 = exactly one row
#define RED_THREADS 1024

// Per-(pair,row) weighted contributions. Deterministic fixed-order final sum.
__device__ float g_partials[NPAIR * BB];

// Blackwell 256-bit streaming load (evict-first): 8 floats, 32B-aligned address.
__device__ __forceinline__ void ldg256_cs(const float* __restrict__ p, float r[8]) {
    asm volatile("ld.global.cs.v8.f32 {%0,%1,%2,%3,%4,%5,%6,%7}, [%8];"
                 : "=f"(r[0]), "=f"(r[1]), "=f"(r[2]), "=f"(r[3]),
                   "=f"(r[4]), "=f"(r[5]), "=f"(r[6]), "=f"(r[7])
                 : "l"(p));
}

__global__ __launch_bounds__(ROW_THREADS)
void wnrmse_row_kernel(const float* __restrict__ o1, const float* __restrict__ t1,
                       const float* __restrict__ o2, const float* __restrict__ t2,
                       const float* __restrict__ o3, const float* __restrict__ t3) {
    const int b = blockIdx.x;   // batch row
    const int p = blockIdx.y;   // pair index
    const int tid = threadIdx.x;

    const float* o = (p == 0) ? o1 : ((p == 1) ? o2 : o3);
    const float* t = (p == 0) ? t1 : ((p == 1) ? t2 : t3);

    // Each thread owns floats [tid*8, tid*8+8) of the row: 256*8 = 2048 ✓
    const float* orow = o + (size_t)b * NN + tid * 8;
    const float* trow = t + (size_t)b * NN + tid * 8;

    // 2 front-batched 256-bit loads (one per tensor).
    float a[8], bb[8];
    ldg256_cs(orow, a);
    ldg256_cs(trow, bb);

    float ssq = 0.0f, tmax = -FLT_MAX, tmin = FLT_MAX;
    #pragma unroll
    for (int i = 0; i < 8; i++) {
        float d = a[i] - bb[i];
        ssq = fmaf(d, d, ssq);
        tmax = fmaxf(tmax, bb[i]);
        tmin = fminf(tmin, bb[i]);
    }

    // Intra-warp reduce
    #pragma unroll
    for (int s = 16; s > 0; s >>= 1) {
        ssq  += __shfl_xor_sync(0xFFFFFFFFu, ssq,  s);
        tmax  = fmaxf(tmax, __shfl_xor_sync(0xFFFFFFFFu, tmax, s));
        tmin  = fminf(tmin, __shfl_xor_sync(0xFFFFFFFFu, tmin, s));
    }

    // Cross-warp reduce (8 warps)
    __shared__ float s_ssq[8], s_max[8], s_min[8];
    const int w = tid >> 5, l = tid & 31;
    if (l == 0) { s_ssq[w] = ssq; s_max[w] = tmax; s_min[w] = tmin; }
    __syncthreads();

    if (tid == 0) {
        float sa = ((s_ssq[0] + s_ssq[1]) + (s_ssq[2] + s_ssq[3]))
                 + ((s_ssq[4] + s_ssq[5]) + (s_ssq[6] + s_ssq[7]));
        float mx = fmaxf(fmaxf(fmaxf(s_max[0], s_max[1]), fmaxf(s_max[2], s_max[3])),
                         fmaxf(fmaxf(s_max[4], s_max[5]), fmaxf(s_max[6], s_max[7])));
        float mn = fminf(fminf(fminf(s_min[0], s_min[1]), fminf(s_min[2], s_min[3])),
                         fminf(fminf(s_min[4], s_min[5]), fminf(s_min[6], s_min[7])));
        const float wgt = (p == 0) ? 0.5f : 0.25f;
        g_partials[p * BB + b] = wgt * sqrtf(sa * (1.0f / NN)) / (mx - mn);
    }
}

// Tail (PDL): overlaps its launch front-end with the primary's drain.
__global__ __launch_bounds__(RED_THREADS)
void wnrmse_reduce_kernel(float* __restrict__ out) {
    cudaGridDependencySynchronize();

    const int tid = threadIdx.x;
    const float4* __restrict__ p4 = reinterpret_cast<const float4*>(g_partials);

    float4 v0 = p4[tid];
    float4 v1 = p4[tid + RED_THREADS];
    float4 v2 = p4[tid + 2 * RED_THREADS];

    float s = ((v0.x + v0.y) + (v0.z + v0.w))
            + ((v1.x + v1.y) + (v1.z + v1.w))
            + ((v2.x + v2.y) + (v2.z + v2.w));

    #pragma unroll
    for (int sh = 16; sh > 0; sh >>= 1)
        s += __shfl_xor_sync(0xFFFFFFFFu, s, sh);

    __shared__ float s_part[32];
    const int w = tid >> 5, l = tid & 31;
    if (l == 0) s_part[w] = s;
    __syncthreads();
    if (w == 0) {
        float a = s_part[l];   // exactly 32 warps
        #pragma unroll
        for (int sh = 16; sh > 0; sh >>= 1)
            a += __shfl_xor_sync(0xFFFFFFFFu, a, sh);
        if (l == 0) out[0] = a * (1.0f / BB);
    }
}

extern "C" void kernel_launch(void* const* d_in, const int* in_sizes, int n_in,
                              void* d_out, int out_size) {
    const float* o1 = (const float*)d_in[0];
    const float* t1 = (const float*)d_in[1];
    const float* o2 = (const float*)d_in[2];
    const float* t2 = (const float*)d_in[3];
    const float* o3 = (const float*)d_in[4];
    const float* t3 = (const float*)d_in[5];
    float* out = (float*)d_out;

    dim3 grid(BB, NPAIR);
    wnrmse_row_kernel<<<grid, ROW_THREADS>>>(o1, t1, o2, t2, o3, t3);

    cudaLaunchConfig_t cfg = {};
    cfg.gridDim = dim3(1, 1, 1);
    cfg.blockDim = dim3(RED_THREADS, 1, 1);
    cfg.dynamicSmemBytes = 0;
    cfg.stream = 0;
    cudaLaunchAttribute attrs[1];
    attrs[0].id = cudaLaunchAttributeProgrammaticStreamSerialization;
    attrs[0].val.programmaticStreamSerializationAllowed = 1;
    cfg.attrs = attrs;
    cfg.numAttrs = 1;
    cudaLaunchKernelEx(&cfg, wnrmse_reduce_kernel, out);
}

// round 13
// speedup vs baseline: 1.0072x; 1.0072x over previous
#include <cuda_runtime.h>
#include <float.h>

#define BB 4096
#define NN 2048
#define NPAIR 3
#define ROW_THREADS 256
#define NWORK (BB * NPAIR)        // 12288 worker CTAs
#define NBLOCKS (NWORK + 1)       // +1 watcher (bid 0)
#define NCTR 64                   // spread completion counters
#define CTR_STRIDE 32             // 32 u32 = 128B between counters

__device__ float g_partials[NPAIR * BB];
__device__ unsigned int g_counts[NCTR * CTR_STRIDE];   // zero-initialized

// 128-bit streaming load (evict-first): data is read exactly once.
__device__ __forceinline__ float4 ldg128_cs(const float4* __restrict__ p) {
    float4 v;
    asm volatile("ld.global.cs.v4.f32 {%0,%1,%2,%3}, [%4];"
                 : "=f"(v.x), "=f"(v.y), "=f"(v.z), "=f"(v.w)
                 : "l"(p));
    return v;
}

__global__ __launch_bounds__(ROW_THREADS)
void wnrmse_kernel(const float* __restrict__ o1, const float* __restrict__ t1,
                   const float* __restrict__ o2, const float* __restrict__ t2,
                   const float* __restrict__ o3, const float* __restrict__ t3,
                   float* __restrict__ out) {
    const int tid = threadIdx.x;
    const int w = tid >> 5, l = tid & 31;

    if (blockIdx.x == 0) {
        // ---- Watcher: warp 0 polls the 64 spread counters; others nap at the bar ----
        if (w == 0) {
            for (;;) {
                unsigned c0, c1;
                asm volatile("ld.relaxed.gpu.global.u32 %0, [%1];"
                             : "=r"(c0) : "l"(&g_counts[l * CTR_STRIDE]) : "memory");
                asm volatile("ld.relaxed.gpu.global.u32 %0, [%1];"
                             : "=r"(c1) : "l"(&g_counts[(l + 32) * CTR_STRIDE]) : "memory");
                unsigned s = c0 + c1;
                #pragma unroll
                for (int sh = 16; sh > 0; sh >>= 1)
                    s += __shfl_xor_sync(0xFFFFFFFFu, s, sh);
                if (__shfl_sync(0xFFFFFFFFu, s, 0) == (unsigned)NWORK) break;
                __nanosleep(100);
            }
            // Acquire: pairs with workers' red.release (observed via relaxed reads).
            asm volatile("fence.acq_rel.gpu;" ::: "memory");
        }
        __syncthreads();

        // Fixed-order reduction: 12288 floats = 3072 float4; 256 thr -> 12 each.
        const float4* __restrict__ p4 = reinterpret_cast<const float4*>(g_partials);
        float s = 0.0f;
        #pragma unroll
        for (int i = 0; i < 12; i++) {
            float4 v = p4[tid + i * ROW_THREADS];
            s += (v.x + v.y) + (v.z + v.w);
        }
        #pragma unroll
        for (int sh = 16; sh > 0; sh >>= 1)
            s += __shfl_xor_sync(0xFFFFFFFFu, s, sh);

        __shared__ float s_fin[8];
        if (l == 0) s_fin[w] = s;
        __syncthreads();
        if (tid == 0) {
            float a = ((s_fin[0] + s_fin[1]) + (s_fin[2] + s_fin[3]))
                    + ((s_fin[4] + s_fin[5]) + (s_fin[6] + s_fin[7]));
            out[0] = a * (1.0f / BB);
        }
        // Reset counters for next graph replay (all arrivals already observed).
        if (tid < NCTR) g_counts[tid * CTR_STRIDE] = 0;
        return;
    }

    // ---- Worker: identical streaming to the R11 winner ----
    const int idx = blockIdx.x - 1;
    const int b = idx & (BB - 1);
    const int p = idx >> 12;

    const float* o = (p == 0) ? o1 : ((p == 1) ? o2 : o3);
    const float* t = (p == 0) ? t1 : ((p == 1) ? t2 : t3);

    const float4* __restrict__ o4 = reinterpret_cast<const float4*>(o + (size_t)b * NN);
    const float4* __restrict__ t4 = reinterpret_cast<const float4*>(t + (size_t)b * NN);

    float4 ov0 = ldg128_cs(o4 + tid);
    float4 tv0 = ldg128_cs(t4 + tid);
    float4 ov1 = ldg128_cs(o4 + tid + ROW_THREADS);
    float4 tv1 = ldg128_cs(t4 + tid + ROW_THREADS);

    float ssq = 0.0f, tmax = -FLT_MAX, tmin = FLT_MAX;
    {
        float d;
        d = ov0.x - tv0.x; ssq = fmaf(d, d, ssq); tmax = fmaxf(tmax, tv0.x); tmin = fminf(tmin, tv0.x);
        d = ov0.y - tv0.y; ssq = fmaf(d, d, ssq); tmax = fmaxf(tmax, tv0.y); tmin = fminf(tmin, tv0.y);
        d = ov0.z - tv0.z; ssq = fmaf(d, d, ssq); tmax = fmaxf(tmax, tv0.z); tmin = fminf(tmin, tv0.z);
        d = ov0.w - tv0.w; ssq = fmaf(d, d, ssq); tmax = fmaxf(tmax, tv0.w); tmin = fminf(tmin, tv0.w);
        d = ov1.x - tv1.x; ssq = fmaf(d, d, ssq); tmax = fmaxf(tmax, tv1.x); tmin = fminf(tmin, tv1.x);
        d = ov1.y - tv1.y; ssq = fmaf(d, d, ssq); tmax = fmaxf(tmax, tv1.y); tmin = fminf(tmin, tv1.y);
        d = ov1.z - tv1.z; ssq = fmaf(d, d, ssq); tmax = fmaxf(tmax, tv1.z); tmin = fminf(tmin, tv1.z);
        d = ov1.w - tv1.w; ssq = fmaf(d, d, ssq); tmax = fmaxf(tmax, tv1.w); tmin = fminf(tmin, tv1.w);
    }

    #pragma unroll
    for (int s = 16; s > 0; s >>= 1) {
        ssq  += __shfl_xor_sync(0xFFFFFFFFu, ssq,  s);
        tmax  = fmaxf(tmax, __shfl_xor_sync(0xFFFFFFFFu, tmax, s));
        tmin  = fminf(tmin, __shfl_xor_sync(0xFFFFFFFFu, tmin, s));
    }

    __shared__ float s_ssq[8], s_max[8], s_min[8];
    if (l == 0) { s_ssq[w] = ssq; s_max[w] = tmax; s_min[w] = tmin; }
    __syncthreads();

    if (tid == 0) {
        float a  = ((s_ssq[0] + s_ssq[1]) + (s_ssq[2] + s_ssq[3]))
                 + ((s_ssq[4] + s_ssq[5]) + (s_ssq[6] + s_ssq[7]));
        float mx = fmaxf(fmaxf(fmaxf(s_max[0], s_max[1]), fmaxf(s_max[2], s_max[3])),
                         fmaxf(fmaxf(s_max[4], s_max[5]), fmaxf(s_max[6], s_max[7])));
        float mn = fminf(fminf(fminf(s_min[0], s_min[1]), fminf(s_min[2], s_min[3])),
                         fminf(fminf(s_min[4], s_min[5]), fminf(s_min[6], s_min[7])));
        const float wgt = (p == 0) ? 0.5f : 0.25f;
        g_partials[idx] = wgt * sqrtf(a * (1.0f / NN)) / (mx - mn);

        // Fire-and-forget release to a SPREAD counter: no return, no serialization.
        asm volatile("red.release.gpu.global.add.u32 [%0], %1;"
                     :: "l"(&g_counts[(idx & (NCTR - 1)) * CTR_STRIDE]), "r"(1u)
                     : "memory");
    }
}

extern "C" void kernel_launch(void* const* d_in, const int* in_sizes, int n_in,
                              void* d_out, int out_size) {
    const float* o1 = (const float*)d_in[0];
    const float* t1 = (const float*)d_in[1];
    const float* o2 = (const float*)d_in[2];
    const float* t2 = (const float*)d_in[3];
    const float* o3 = (const float*)d_in[4];
    const float* t3 = (const float*)d_in[5];
    float* out = (float*)d_out;

    wnrmse_kernel<<<NBLOCKS, ROW_THREADS>>>(o1, t1, o2, t2, o3, t3, out);
}

// round 14
// speedup vs baseline: 1.0211x; 1.0138x over previous
#include <cuda_runtime.h>
#include <float.h>

#define BB 4096
#define NN 2048
#define NPAIR 3
#define ROW_THREADS 256
#define RED_THREADS 256

// Per-(pair,row) weighted contributions. Deterministic fixed-order final sum.
__device__ float g_partials[NPAIR * BB];

// 128-bit streaming load (evict-first): data is read exactly once.
__device__ __forceinline__ float4 ldg128_cs(const float4* __restrict__ p) {
    float4 v;
    asm volatile("ld.global.cs.v4.f32 {%0,%1,%2,%3}, [%4];"
                 : "=f"(v.x), "=f"(v.y), "=f"(v.z), "=f"(v.w)
                 : "l"(p));
    return v;
}

__global__ __launch_bounds__(ROW_THREADS)
void wnrmse_row_kernel(const float* __restrict__ o1, const float* __restrict__ t1,
                       const float* __restrict__ o2, const float* __restrict__ t2,
                       const float* __restrict__ o3, const float* __restrict__ t3) {
    const int b = blockIdx.x;   // batch row
    const int p = blockIdx.y;   // pair index
    const int tid = threadIdx.x;

    const float* o = (p == 0) ? o1 : ((p == 1) ? o2 : o3);
    const float* t = (p == 0) ? t1 : ((p == 1) ? t2 : t3);

    const float4* __restrict__ o4 = reinterpret_cast<const float4*>(o + (size_t)b * NN);
    const float4* __restrict__ t4 = reinterpret_cast<const float4*>(t + (size_t)b * NN);

    // 2048 floats = 512 float4; 256 threads -> 2 float4 each. Front-batch all 4 loads.
    float4 ov0 = ldg128_cs(o4 + tid);
    float4 tv0 = ldg128_cs(t4 + tid);
    float4 ov1 = ldg128_cs(o4 + tid + ROW_THREADS);
    float4 tv1 = ldg128_cs(t4 + tid + ROW_THREADS);

    float ssq = 0.0f, tmax = -FLT_MAX, tmin = FLT_MAX;
    {
        float d;
        d = ov0.x - tv0.x; ssq = fmaf(d, d, ssq); tmax = fmaxf(tmax, tv0.x); tmin = fminf(tmin, tv0.x);
        d = ov0.y - tv0.y; ssq = fmaf(d, d, ssq); tmax = fmaxf(tmax, tv0.y); tmin = fminf(tmin, tv0.y);
        d = ov0.z - tv0.z; ssq = fmaf(d, d, ssq); tmax = fmaxf(tmax, tv0.z); tmin = fminf(tmin, tv0.z);
        d = ov0.w - tv0.w; ssq = fmaf(d, d, ssq); tmax = fmaxf(tmax, tv0.w); tmin = fminf(tmin, tv0.w);
        d = ov1.x - tv1.x; ssq = fmaf(d, d, ssq); tmax = fmaxf(tmax, tv1.x); tmin = fminf(tmin, tv1.x);
        d = ov1.y - tv1.y; ssq = fmaf(d, d, ssq); tmax = fmaxf(tmax, tv1.y); tmin = fminf(tmin, tv1.y);
        d = ov1.z - tv1.z; ssq = fmaf(d, d, ssq); tmax = fmaxf(tmax, tv1.z); tmin = fminf(tmin, tv1.z);
        d = ov1.w - tv1.w; ssq = fmaf(d, d, ssq); tmax = fmaxf(tmax, tv1.w); tmin = fminf(tmin, tv1.w);
    }

    // Intra-warp reduce
    #pragma unroll
    for (int s = 16; s > 0; s >>= 1) {
        ssq  += __shfl_xor_sync(0xFFFFFFFFu, ssq,  s);
        tmax  = fmaxf(tmax, __shfl_xor_sync(0xFFFFFFFFu, tmax, s));
        tmin  = fminf(tmin, __shfl_xor_sync(0xFFFFFFFFu, tmin, s));
    }

    // Cross-warp reduce (8 warps)
    __shared__ float s_ssq[8], s_max[8], s_min[8];
    const int w = tid >> 5, l = tid & 31;
    if (l == 0) { s_ssq[w] = ssq; s_max[w] = tmax; s_min[w] = tmin; }
    __syncthreads();

    if (tid == 0) {
        float a  = ((s_ssq[0] + s_ssq[1]) + (s_ssq[2] + s_ssq[3]))
                 + ((s_ssq[4] + s_ssq[5]) + (s_ssq[6] + s_ssq[7]));
        float mx = fmaxf(fmaxf(fmaxf(s_max[0], s_max[1]), fmaxf(s_max[2], s_max[3])),
                         fmaxf(fmaxf(s_max[4], s_max[5]), fmaxf(s_max[6], s_max[7])));
        float mn = fminf(fminf(fminf(s_min[0], s_min[1]), fminf(s_min[2], s_min[3])),
                         fminf(fminf(s_min[4], s_min[5]), fminf(s_min[6], s_min[7])));
        const float wgt = (p == 0) ? 0.5f : 0.25f;
        g_partials[p * BB + b] = wgt * sqrtf(a * (1.0f / NN)) / (mx - mn);
    }
}

// Tail (PDL): 256 threads x 12 front-batched loads -> one latency round.
__global__ __launch_bounds__(RED_THREADS)
void wnrmse_reduce_kernel(float* __restrict__ out) {
    cudaGridDependencySynchronize();

    const int tid = threadIdx.x;
    const float4* __restrict__ p4 = reinterpret_cast<const float4*>(g_partials);

    // 12288 floats = 3072 float4; 256 threads -> 12 each, all independent.
    float4 v[12];
    #pragma unroll
    for (int i = 0; i < 12; i++) v[i] = p4[tid + i * RED_THREADS];

    float s = 0.0f;
    #pragma unroll
    for (int i = 0; i < 12; i++)
        s += (v[i].x + v[i].y) + (v[i].z + v[i].w);

    #pragma unroll
    for (int sh = 16; sh > 0; sh >>= 1)
        s += __shfl_xor_sync(0xFFFFFFFFu, s, sh);

    __shared__ float s_part[8];
    const int w = tid >> 5, l = tid & 31;
    if (l == 0) s_part[w] = s;
    __syncthreads();
    if (tid == 0) {
        float a = ((s_part[0] + s_part[1]) + (s_part[2] + s_part[3]))
                + ((s_part[4] + s_part[5]) + (s_part[6] + s_part[7]));
        out[0] = a * (1.0f / BB);
    }
}

extern "C" void kernel_launch(void* const* d_in, const int* in_sizes, int n_in,
                              void* d_out, int out_size) {
    const float* o1 = (const float*)d_in[0];
    const float* t1 = (const float*)d_in[1];
    const float* o2 = (const float*)d_in[2];
    const float* t2 = (const float*)d_in[3];
    const float* o3 = (const float*)d_in[4];
    const float* t3 = (const float*)d_in[5];
    float* out = (float*)d_out;

    dim3 grid(BB, NPAIR);
    wnrmse_row_kernel<<<grid, ROW_THREADS>>>(o1, t1, o2, t2, o3, t3);

    cudaLaunchConfig_t cfg = {};
    cfg.gridDim = dim3(1, 1, 1);
    cfg.blockDim = dim3(RED_THREADS, 1, 1);
    cfg.dynamicSmemBytes = 0;
    cfg.stream = 0;
    cudaLaunchAttribute attrs[1];
    attrs[0].id = cudaLaunchAttributeProgrammaticStreamSerialization;
    attrs[0].val.programmaticStreamSerializationAllowed = 1;
    cfg.attrs = attrs;
    cfg.numAttrs = 1;
    cudaLaunchKernelEx(&cfg, wnrmse_reduce_kernel, out);
}

// round 15
// speedup vs baseline: 1.0692x; 1.0471x over previous
#include <cuda_runtime.h>
#include <float.h>

#define BB 4096
#define NN 2048
#define NPAIR 3
#define ROW_THREADS 256
#define RED_THREADS 1024

// Per-(pair,row) weighted contributions. Deterministic fixed-order final sum.
__device__ float g_partials[NPAIR * BB];

// 128-bit streaming load (evict-first): data is read exactly once.
__device__ __forceinline__ float4 ldg128_cs(const float4* __restrict__ p) {
    float4 v;
    asm volatile("ld.global.cs.v4.f32 {%0,%1,%2,%3}, [%4];"
                 : "=f"(v.x), "=f"(v.y), "=f"(v.z), "=f"(v.w)
                 : "l"(p));
    return v;
}

__global__ __launch_bounds__(ROW_THREADS)
void wnrmse_row_kernel(const float* __restrict__ o1, const float* __restrict__ t1,
                       const float* __restrict__ o2, const float* __restrict__ t2,
                       const float* __restrict__ o3, const float* __restrict__ t3) {
    const int b = blockIdx.x;   // batch row
    const int p = blockIdx.y;   // pair index
    const int tid = threadIdx.x;

    const float* o = (p == 0) ? o1 : ((p == 1) ? o2 : o3);
    const float* t = (p == 0) ? t1 : ((p == 1) ? t2 : t3);

    const float4* __restrict__ o4 = reinterpret_cast<const float4*>(o + (size_t)b * NN);
    const float4* __restrict__ t4 = reinterpret_cast<const float4*>(t + (size_t)b * NN);

    // 2048 floats = 512 float4; 256 threads -> 2 float4 each. Front-batch all 4 loads.
    float4 ov0 = ldg128_cs(o4 + tid);
    float4 tv0 = ldg128_cs(t4 + tid);
    float4 ov1 = ldg128_cs(o4 + tid + ROW_THREADS);
    float4 tv1 = ldg128_cs(t4 + tid + ROW_THREADS);

    float ssq = 0.0f, tmax = -FLT_MAX, tmin = FLT_MAX;
    {
        float d;
        d = ov0.x - tv0.x; ssq = fmaf(d, d, ssq); tmax = fmaxf(tmax, tv0.x); tmin = fminf(tmin, tv0.x);
        d = ov0.y - tv0.y; ssq = fmaf(d, d, ssq); tmax = fmaxf(tmax, tv0.y); tmin = fminf(tmin, tv0.y);
        d = ov0.z - tv0.z; ssq = fmaf(d, d, ssq); tmax = fmaxf(tmax, tv0.z); tmin = fminf(tmin, tv0.z);
        d = ov0.w - tv0.w; ssq = fmaf(d, d, ssq); tmax = fmaxf(tmax, tv0.w); tmin = fminf(tmin, tv0.w);
        d = ov1.x - tv1.x; ssq = fmaf(d, d, ssq); tmax = fmaxf(tmax, tv1.x); tmin = fminf(tmin, tv1.x);
        d = ov1.y - tv1.y; ssq = fmaf(d, d, ssq); tmax = fmaxf(tmax, tv1.y); tmin = fminf(tmin, tv1.y);
        d = ov1.z - tv1.z; ssq = fmaf(d, d, ssq); tmax = fmaxf(tmax, tv1.z); tmin = fminf(tmin, tv1.z);
        d = ov1.w - tv1.w; ssq = fmaf(d, d, ssq); tmax = fmaxf(tmax, tv1.w); tmin = fminf(tmin, tv1.w);
    }

    // Intra-warp reduce
    #pragma unroll
    for (int s = 16; s > 0; s >>= 1) {
        ssq  += __shfl_xor_sync(0xFFFFFFFFu, ssq,  s);
        tmax  = fmaxf(tmax, __shfl_xor_sync(0xFFFFFFFFu, tmax, s));
        tmin  = fminf(tmin, __shfl_xor_sync(0xFFFFFFFFu, tmin, s));
    }

    // Cross-warp reduce (8 warps)
    __shared__ float s_ssq[8], s_max[8], s_min[8];
    const int w = tid >> 5, l = tid & 31;
    if (l == 0) { s_ssq[w] = ssq; s_max[w] = tmax; s_min[w] = tmin; }
    __syncthreads();

    if (tid == 0) {
        float a  = ((s_ssq[0] + s_ssq[1]) + (s_ssq[2] + s_ssq[3]))
                 + ((s_ssq[4] + s_ssq[5]) + (s_ssq[6] + s_ssq[7]));
        float mx = fmaxf(fmaxf(fmaxf(s_max[0], s_max[1]), fmaxf(s_max[2], s_max[3])),
                         fmaxf(fmaxf(s_max[4], s_max[5]), fmaxf(s_max[6], s_max[7])));
        float mn = fminf(fminf(fminf(s_min[0], s_min[1]), fminf(s_min[2], s_min[3])),
                         fminf(fminf(s_min[4], s_min[5]), fminf(s_min[6], s_min[7])));
        const float wgt = (p == 0) ? 0.5f : 0.25f;
        g_partials[p * BB + b] = wgt * sqrtf(a * (1.0f / NN)) / (mx - mn);
    }
}

// Tail: plain launch (best-measured config), 1024 thr x 3 front-batched float4.
__global__ __launch_bounds__(RED_THREADS)
void wnrmse_reduce_kernel(float* __restrict__ out) {
    const int tid = threadIdx.x;
    const float4* __restrict__ p4 = reinterpret_cast<const float4*>(g_partials);

    float4 v0 = p4[tid];
    float4 v1 = p4[tid + RED_THREADS];
    float4 v2 = p4[tid + 2 * RED_THREADS];

    float s = ((v0.x + v0.y) + (v0.z + v0.w))
            + ((v1.x + v1.y) + (v1.z + v1.w))
            + ((v2.x + v2.y) + (v2.z + v2.w));

    #pragma unroll
    for (int sh = 16; sh > 0; sh >>= 1)
        s += __shfl_xor_sync(0xFFFFFFFFu, s, sh);

    __shared__ float s_part[32];
    const int w = tid >> 5, l = tid & 31;
    if (l == 0) s_part[w] = s;
    __syncthreads();
    if (w == 0) {
        float a = s_part[l];   // exactly 32 warps
        #pragma unroll
        for (int sh = 16; sh > 0; sh >>= 1)
            a += __shfl_xor_sync(0xFFFFFFFFu, a, sh);
        if (l == 0) out[0] = a * (1.0f / BB);
    }
}

extern "C" void kernel_launch(void* const* d_in, const int* in_sizes, int n_in,
                              void* d_out, int out_size) {
    const float* o1 = (const float*)d_in[0];
    const float* t1 = (const float*)d_in[1];
    const float* o2 = (const float*)d_in[2];
    const float* t2 = (const float*)d_in[3];
    const float* o3 = (const float*)d_in[4];
    const float* t3 = (const float*)d_in[5];
    float* out = (float*)d_out;

    dim3 grid(BB, NPAIR);
    wnrmse_row_kernel<<<grid, ROW_THREADS>>>(o1, t1, o2, t2, o3, t3);
    wnrmse_reduce_kernel<<<1, RED_THREADS>>>(out);
}